// round 8
// baseline (speedup 1.0000x reference)
#include <cuda_runtime.h>

// ---------------- problem constants ----------------
#define NL   16
#define DM   1024
#define NH   16
#define NKV  8
#define DH   128
#define SEQ  4096
#define FF   4096
#define VOC  32000

#define NB   256   // mega-kernel blocks (all resident: 2/SM x 148 = 296 >= 256)
#define NPQ  32    // qkv row partials (32 rows each)
#define NPO  64    // wo row partials
#define NPG  32    // gate/up row partials
#define NPD  128   // wd row partials
#define NPL  8     // lm row partials
#define NCH  32    // attention chunks of 128
#define NCPY 65    // copy slices

// ---------------- scratch ----------------
__device__ __align__(16) float g_x[DM];
__device__ float g_ss[8];
__device__ __align__(16) float g_qkv_part[NPQ][4096];
__device__ float g_attn_m[NKV][NCH][2];
__device__ float g_attn_l[NKV][NCH][2];
__device__ __align__(16) float g_attn_o[NKV][NCH][2][DH];
__device__ __align__(16) float g_o_part[NPO][DM];
__device__ __align__(16) float g_gu_part[NPG][2*FF];
__device__ __align__(16) float g_d_part[NPD][DM];
__device__ __align__(16) float g_lm_part[NPL][VOC];
__device__ float g_amax_val[128];
__device__ int   g_amax_idx[128];

// grid barrier state (returns to steady state every launch)
__device__ unsigned g_cnt;
__device__ volatile unsigned g_gen;

__device__ __forceinline__ void fma4(float4& acc, float a, const float4& w) {
    acc.x += a * w.x; acc.y += a * w.y; acc.z += a * w.z; acc.w += a * w.w;
}

__device__ __forceinline__ void gbar() {
    __threadfence();          // release: flush this thread's writes (+L1 inval)
    __syncthreads();
    if (threadIdx.x == 0) {
        unsigned my = g_gen;
        if (atomicAdd(&g_cnt, 1u) == NB - 1u) {
            g_cnt = 0u;
            __threadfence();
            g_gen = my + 1u;
        } else {
            while (g_gen == my) { }
        }
    }
    __syncthreads();
    __threadfence();          // acquire: invalidate stale L1 lines
}

// ---------------- copy slice (scalar, skips rows at pos) ----------------
__device__ void do_copy(int cb, int ncb, int tid, int slice, int pos,
                        const float* __restrict__ a, const float* __restrict__ b,
                        float* __restrict__ oa, float* __restrict__ ob)
{
    const long N = (long)NL * NKV * SEQ * DH;      // 67108864
    const long CH = (N + NCPY - 1) / NCPY;
    long beg = (long)slice * CH;
    long end = beg + CH; if (end > N) end = N;
    long stp = (long)ncb * 256;
    for (long e = beg + (long)cb * 256 + tid; e < end; e += stp) {
        int s = (int)((e >> 7) & (SEQ - 1));
        if (s != pos) {
            __stcs(oa + e, __ldcs(a + e));
            __stcs(ob + e, __ldcs(b + e));
        }
    }
}

// ---------------- xred: residual + partial-sum + ss (8 blocks) ----------------
// mode 0: x = embed row; 1: x += sum d_part; 2: x += sum o_part
__device__ void phase_xred(int bid, int tid, int mode,
                           const float* __restrict__ emb, int tok, float* sm)
{
    int j = bid * 128 + tid;
    float ss = 0.f;
    if (tid < 128) {
        float x;
        if (mode == 0) x = emb[(long)tok * DM + j];
        else {
            x = g_x[j];
            if (mode == 1) {
                #pragma unroll 16
                for (int i = 0; i < NPD; ++i) x += g_d_part[i][j];
            } else {
                #pragma unroll 16
                for (int i = 0; i < NPO; ++i) x += g_o_part[i][j];
            }
        }
        g_x[j] = x;
        ss = x * x;
    }
    #pragma unroll
    for (int o = 16; o > 0; o >>= 1) ss += __shfl_down_sync(0xffffffffu, ss, o);
    if (tid < 128 && (tid & 31) == 0) sm[tid >> 5] = ss;
    __syncthreads();
    if (tid == 0) g_ss[bid] = sm[0] + sm[1] + sm[2] + sm[3];
}

// ---------------- qkv GEMV (256 blocks: 8 coltiles x 32 rowslices) ----------
__device__ void phase_qkv(int bid, int tid, const float* __restrict__ lnw,
                          const float* __restrict__ Wq, const float* __restrict__ Wk,
                          const float* __restrict__ Wv, float* sm)
{
    int ct = bid & 7, rs = bid >> 3;
    int r0 = rs * 32;
    if (tid == 0) {
        float t = 0.f;
        #pragma unroll
        for (int i = 0; i < 8; ++i) t += g_ss[i];
        sm[32] = rsqrtf(t * (1.0f / DM) + 1e-6f);
    }
    __syncthreads();
    if (tid < 32) sm[tid] = g_x[r0 + tid] * sm[32] * lnw[r0 + tid];
    __syncthreads();
    int j = ct * 512 + tid * 2;
    const float* W; int cols, jj;
    if (j < 2048)      { W = Wq; cols = 2048; jj = j; }
    else if (j < 3072) { W = Wk; cols = 1024; jj = j - 2048; }
    else               { W = Wv; cols = 1024; jj = j - 3072; }
    const float* p = W + (long)r0 * cols + jj;
    float2 acc = {0.f, 0.f};
    #pragma unroll 8
    for (int r = 0; r < 32; ++r) {
        float a = sm[r];
        float2 w = *(const float2*)p;
        acc.x += a * w.x; acc.y += a * w.y;
        p += cols;
    }
    *(float2*)&g_qkv_part[rs][j] = acc;
}

// ---------------- attention (256 blocks: 32 chunks x 8 kv) ----------------
__device__ void phase_attn(int bid, int tid, int layer, int pos,
                           const float* __restrict__ pk, const float* __restrict__ pv,
                           float* __restrict__ ok, float* __restrict__ ov, float* sm)
{
    int kv = bid & 7, ch = bid >> 3;
    int s0 = ch << 7;
    if (s0 > pos) {
        if (tid < 2) g_attn_l[kv][ch][tid] = 0.f;
        return;
    }
    float* shq = sm;            // 256
    float* shk = sm + 256;      // 128
    float* shv = sm + 384;      // 128
    float* shs = sm + 512;      // 256
    float* red = sm + 768;      // 8
    float* shm = sm + 776;      // 2
    int smax = (pos < s0 + 127) ? pos : s0 + 127;
    bool haspos = (ch == (pos >> 7));
    {
        int h = tid >> 7, d = tid & 127;
        float a = 0.f;
        #pragma unroll 8
        for (int i = 0; i < NPQ; ++i) a += g_qkv_part[i][(kv*2 + h)*DH + d];
        shq[h*DH + d] = a;
    }
    if (haspos) {
        int off = (tid < 128) ? (2048 + kv*DH + tid) : (3072 + kv*DH + tid - 128);
        float a = 0.f;
        #pragma unroll 8
        for (int i = 0; i < NPQ; ++i) a += g_qkv_part[i][off];
        if (tid < 128) shk[tid] = a; else shv[tid - 128] = a;
    }
    __syncthreads();
    const float SCALE = 0.08838834764831845f;   // 1/sqrt(128)
    const float LF = 0.14391156831212785f;      // ln(10000)/64
    if (tid < 128) {
        int h = tid >> 6, i = tid & 63;
        float ang = (float)pos * expf(-(float)i * LF);
        float c, s; sincosf(ang, &s, &c);
        float x1 = shq[h*128 + i], x2 = shq[h*128 + i + 64];
        shq[h*128 + i]      = (x1*c - x2*s) * SCALE;
        shq[h*128 + i + 64] = (x2*c + x1*s) * SCALE;
    } else if (haspos && tid < 192) {
        int i = tid - 128;
        float ang = (float)pos * expf(-(float)i * LF);
        float c, s; sincosf(ang, &s, &c);
        float k1 = shk[i], k2 = shk[i + 64];
        shk[i]      = k1*c - k2*s;
        shk[i + 64] = k2*c + k1*s;
    }
    __syncthreads();
    if (haspos) {
        long rb = (((long)layer * NKV + kv) * SEQ + pos) * DH;
        if (tid < 128) ok[rb + tid] = shk[tid];
        else           ov[rb + tid - 128] = shv[tid - 128];
    }
    int warp = tid >> 5, lane = tid & 31;
    float4 q0 = ((const float4*)shq)[lane];
    float4 q1 = ((const float4*)(shq + 128))[lane];
    long kb = ((long)layer * NKV + kv) * SEQ * DH;
    #pragma unroll 2
    for (int it = 0; it < 16; ++it) {
        int sl = (it << 3) + warp;
        int si = s0 + sl;
        if (si <= smax) {
            float4 kk;
            if (si == pos) kk = ((const float4*)shk)[lane];
            else           kk = *(const float4*)(pk + kb + (long)si*DH + lane*4);
            float d0 = q0.x*kk.x + q0.y*kk.y + q0.z*kk.z + q0.w*kk.w;
            float d1 = q1.x*kk.x + q1.y*kk.y + q1.z*kk.z + q1.w*kk.w;
            #pragma unroll
            for (int o = 16; o > 0; o >>= 1) {
                d0 += __shfl_down_sync(0xffffffffu, d0, o);
                d1 += __shfl_down_sync(0xffffffffu, d1, o);
            }
            if (lane == 0) { shs[sl] = d0; shs[128 + sl] = d1; }
        } else if (lane == 0) {
            shs[sl] = -1e30f; shs[128 + sl] = -1e30f;
        }
    }
    __syncthreads();
    int h = tid >> 7, d = tid & 127;
    float v = shs[h*128 + d];
    float m = v;
    #pragma unroll
    for (int o = 16; o > 0; o >>= 1) m = fmaxf(m, __shfl_down_sync(0xffffffffu, m, o));
    if (lane == 0) red[warp] = m;
    __syncthreads();
    if (tid < 2)
        shm[tid] = fmaxf(fmaxf(red[tid*4], red[tid*4+1]), fmaxf(red[tid*4+2], red[tid*4+3]));
    __syncthreads();
    float p = expf(v - shm[h]);
    shs[h*128 + d] = p;
    float l = p;
    #pragma unroll
    for (int o = 16; o > 0; o >>= 1) l += __shfl_down_sync(0xffffffffu, l, o);
    if (lane == 0) red[warp] = l;
    __syncthreads();
    if (tid < 2) {
        g_attn_m[kv][ch][tid] = shm[tid];
        g_attn_l[kv][ch][tid] = red[tid*4] + red[tid*4+1] + red[tid*4+2] + red[tid*4+3];
    }
    int count = smax - s0 + 1;
    int nglob = haspos ? count - 1 : count;
    const float* pvp = pv + kb + (long)s0*DH + d;
    float acc = 0.f;
    int s = 0;
    for (; s + 7 < nglob; s += 8) {
        float acc2 = 0.f;
        #pragma unroll
        for (int u = 0; u < 8; u += 2) {
            acc  += shs[h*128 + s+u]   * pvp[(long)(s+u)*DH];
            acc2 += shs[h*128 + s+u+1] * pvp[(long)(s+u+1)*DH];
        }
        acc += acc2;
    }
    for (; s < nglob; ++s) acc += shs[h*128 + s] * pvp[(long)s*DH];
    if (haspos) acc += shs[h*128 + count - 1] * shv[d];
    g_attn_o[kv][ch][h][d] = acc;
}

// ---------------- wo GEMV + split-softmax combine (64 blocks) --------------
__device__ void phase_wo(int bid, int tid, const float* __restrict__ Wo, float* sm)
{
    float* ml  = sm;        // 64
    float* w   = sm + 64;   // 32
    float* av  = sm + 96;   // 32
    float* idn = sm + 128;  // 1
    int rs = bid, r0 = rs * 32;
    int p = r0 >> 7, kv = p >> 1, hh = p & 1, db = r0 & 127;
    if (tid < 32) { ml[tid] = g_attn_m[kv][tid][hh]; ml[32 + tid] = g_attn_l[kv][tid][hh]; }
    __syncthreads();
    if (tid == 0) {
        float M = -1e30f;
        for (int c = 0; c < NCH; ++c) if (ml[32+c] > 0.f) M = fmaxf(M, ml[c]);
        float den = 0.f;
        for (int c = 0; c < NCH; ++c) {
            float wv = (ml[32+c] > 0.f) ? expf(ml[c] - M) : 0.f;
            w[c] = wv; den += wv * ml[32+c];
        }
        idn[0] = 1.f / den;
    }
    __syncthreads();
    if (tid < 32) {
        float num = 0.f;
        #pragma unroll
        for (int c = 0; c < NCH; ++c) {
            float wv = w[c];
            if (wv != 0.f) num += wv * g_attn_o[kv][c][hh][db + tid];
        }
        av[tid] = num * idn[0];
    }
    __syncthreads();
    int j = tid * 4;
    const float* pw = Wo + (long)r0 * DM + j;
    float4 acc = {0.f,0.f,0.f,0.f};
    #pragma unroll 8
    for (int r = 0; r < 32; ++r)
        fma4(acc, av[r], *(const float4*)(pw + (long)r * DM));
    *(float4*)&g_o_part[rs][j] = acc;
}

// ---------------- gate/up GEMV (256 blocks: 8 coltiles x 32 rowslices) -----
__device__ void phase_gateup(int bid, int tid, const float* __restrict__ lnw,
                             const float* __restrict__ Wg, const float* __restrict__ Wu,
                             float* sm)
{
    int ct = bid & 7, rs = bid >> 3, r0 = rs * 32;
    if (tid == 0) {
        float t = 0.f;
        #pragma unroll
        for (int i = 0; i < 8; ++i) t += g_ss[i];
        sm[32] = rsqrtf(t * (1.0f / DM) + 1e-6f);
    }
    __syncthreads();
    if (tid < 32) sm[tid] = g_x[r0 + tid] * sm[32] * lnw[r0 + tid];
    __syncthreads();
    int j = ct * 1024 + tid * 4;
    const float* W; int jj;
    if (j < FF) { W = Wg; jj = j; } else { W = Wu; jj = j - FF; }
    const float* p = W + (long)r0 * FF + jj;
    float4 acc = {0.f,0.f,0.f,0.f};
    #pragma unroll 8
    for (int r = 0; r < 32; ++r) {
        fma4(acc, sm[r], *(const float4*)p);
        p += FF;
    }
    *(float4*)&g_gu_part[rs][j] = acc;
}

// ---------------- wd GEMV + silu (128 blocks) ----------------
__device__ void phase_wd(int bid, int tid, const float* __restrict__ Wd, float* sm)
{
    int rs = bid, r0 = rs * 32;
    if (tid < 32) {
        float g = 0.f, u = 0.f;
        #pragma unroll 8
        for (int i = 0; i < NPG; ++i) {
            g += g_gu_part[i][r0 + tid];
            u += g_gu_part[i][FF + r0 + tid];
        }
        sm[tid] = (g / (1.f + expf(-g))) * u;
    }
    __syncthreads();
    int j = tid * 4;
    const float* pw = Wd + (long)r0 * DM + j;
    float4 acc = {0.f,0.f,0.f,0.f};
    #pragma unroll 8
    for (int r = 0; r < 32; ++r)
        fma4(acc, sm[r], *(const float4*)(pw + (long)r * DM));
    *(float4*)&g_d_part[rs][j] = acc;
}

// ---------------- the persistent mega kernel ----------------
__global__ void __launch_bounds__(256, 2) k_mega(
    const int* __restrict__ ids, const int* __restrict__ step, const int* __restrict__ plen,
    const float* __restrict__ pk, const float* __restrict__ pv,
    const float* __restrict__ emb,
    const float* __restrict__ Wq, const float* __restrict__ Wk,
    const float* __restrict__ Wv, const float* __restrict__ Wo,
    const float* __restrict__ Wg, const float* __restrict__ Wu,
    const float* __restrict__ Wd,
    const float* __restrict__ ln1, const float* __restrict__ ln2,
    float* __restrict__ ok, float* __restrict__ ov)
{
    __shared__ __align__(16) float sm[800];
    int bid = blockIdx.x, tid = threadIdx.x;
    int pos = step[0] + plen[0];
    int tok = ids[0];

    for (int l = 0; l < NL; ++l) {
        // XRED1 (+ copy slice 4l)
        if (bid < 8) phase_xred(bid, tid, l == 0 ? 0 : 1, emb, tok, sm);
        else         do_copy(bid - 8, NB - 8, tid, l*4 + 0, pos, pk, pv, ok, ov);
        gbar();
        phase_qkv(bid, tid, ln1 + (long)l * DM,
                  Wq + (long)l * DM * 2048,
                  Wk + (long)l * DM * 1024,
                  Wv + (long)l * DM * 1024, sm);
        gbar();
        phase_attn(bid, tid, l, pos, pk, pv, ok, ov, sm);
        gbar();
        if (bid < 64) phase_wo(bid, tid, Wo + (long)l * 2048 * DM, sm);
        else          do_copy(bid - 64, NB - 64, tid, l*4 + 1, pos, pk, pv, ok, ov);
        gbar();
        // XRED2 (+ copy slice 4l+2)
        if (bid < 8) phase_xred(bid, tid, 2, emb, tok, sm);
        else         do_copy(bid - 8, NB - 8, tid, l*4 + 2, pos, pk, pv, ok, ov);
        gbar();
        phase_gateup(bid, tid, ln2 + (long)l * DM,
                     Wg + (long)l * DM * FF, Wu + (long)l * DM * FF, sm);
        gbar();
        if (bid < 128) phase_wd(bid, tid, Wd + (long)l * FF * DM, sm);
        else           do_copy(bid - 128, NB - 128, tid, l*4 + 3, pos, pk, pv, ok, ov);
        gbar();
    }
    // final xred (x += d_part) + last copy slice; k_lm (next launch) consumes
    if (bid < 8) phase_xred(bid, tid, 1, emb, tok, sm);
    else         do_copy(bid - 8, NB - 8, tid, 64, pos, pk, pv, ok, ov);
}

// ---------------- LM head GEMV (separate launch) ----------------
__global__ void __launch_bounds__(256) k_lm(
    const float* __restrict__ lnf, const float* __restrict__ Wlm)
{
    __shared__ float n[128];
    __shared__ float srstd;
    int tid = threadIdx.x;
    int r0 = blockIdx.y * 128;
    if (tid == 0) {
        float t = 0.f;
        #pragma unroll
        for (int i = 0; i < 8; ++i) t += g_ss[i];
        srstd = rsqrtf(t * (1.0f / DM) + 1e-6f);
    }
    __syncthreads();
    if (tid < 128) n[tid] = g_x[r0 + tid] * srstd * lnf[r0 + tid];
    __syncthreads();
    int j = blockIdx.x * 1024 + tid * 4;
    if (j >= VOC) return;
    const float* p = Wlm + (long)r0 * VOC + j;
    float4 acc = {0.f,0.f,0.f,0.f};
    #pragma unroll 8
    for (int r = 0; r < 128; ++r) {
        fma4(acc, n[r], *(const float4*)p);
        p += VOC;
    }
    *(float4*)&g_lm_part[blockIdx.y][j] = acc;
}

// ---------------- argmax ----------------
__global__ void __launch_bounds__(256) k_amax1()
{
    __shared__ float sv[256];
    __shared__ int   si[256];
    int t = threadIdx.x;
    int j = blockIdx.x * 256 + t;
    float v = 0.f;
    #pragma unroll
    for (int i = 0; i < NPL; ++i) v += g_lm_part[i][j];
    sv[t] = v; si[t] = j;
    __syncthreads();
    for (int o = 128; o > 0; o >>= 1) {
        if (t < o) {
            float v2 = sv[t + o]; int i2 = si[t + o];
            if (v2 > sv[t] || (v2 == sv[t] && i2 < si[t])) { sv[t] = v2; si[t] = i2; }
        }
        __syncthreads();
    }
    if (t == 0) { g_amax_val[blockIdx.x] = sv[0]; g_amax_idx[blockIdx.x] = si[0]; }
}

__global__ void __launch_bounds__(128) k_amax2(float* __restrict__ out)
{
    __shared__ float sv[128];
    __shared__ int   si[128];
    int t = threadIdx.x;
    if (t < 125) { sv[t] = g_amax_val[t]; si[t] = g_amax_idx[t]; }
    else         { sv[t] = -1e38f;        si[t] = 0x7fffffff; }
    __syncthreads();
    for (int o = 64; o > 0; o >>= 1) {
        if (t < o) {
            float v2 = sv[t + o]; int i2 = si[t + o];
            if (v2 > sv[t] || (v2 == sv[t] && i2 < si[t])) { sv[t] = v2; si[t] = i2; }
        }
        __syncthreads();
    }
    if (t == 0) out[0] = (float)si[0];
}

// ---------------- launch ----------------
extern "C" void kernel_launch(void* const* d_in, const int* in_sizes, int n_in,
                              void* d_out, int out_size)
{
    const int*   ids  = (const int*)  d_in[0];
    const int*   step = (const int*)  d_in[1];
    const int*   plen = (const int*)  d_in[2];
    const float* pk   = (const float*)d_in[3];
    const float* pv   = (const float*)d_in[4];
    const float* emb  = (const float*)d_in[5];
    const float* Wq   = (const float*)d_in[6];
    const float* Wk   = (const float*)d_in[7];
    const float* Wv   = (const float*)d_in[8];
    const float* Wo   = (const float*)d_in[9];
    const float* Wg   = (const float*)d_in[10];
    const float* Wu   = (const float*)d_in[11];
    const float* Wd   = (const float*)d_in[12];
    const float* ln1  = (const float*)d_in[13];
    const float* ln2  = (const float*)d_in[14];
    const float* lnf  = (const float*)d_in[15];
    const float* Wlm  = (const float*)d_in[16];

    float* out = (float*)d_out;
    const long CACHE = (long)NL * NKV * SEQ * DH;
    float* ok = out + 1;
    float* ov = out + 1 + CACHE;

    k_mega<<<NB, 256>>>(ids, step, plen, pk, pv, emb,
                        Wq, Wk, Wv, Wo, Wg, Wu, Wd, ln1, ln2, ok, ov);
    k_lm<<<dim3(32, NPL), 256>>>(lnf, Wlm);
    k_amax1<<<125, 256>>>();
    k_amax2<<<1, 128>>>(out);
}

// round 11
// speedup vs baseline: 1.8560x; 1.8560x over previous
#include <cuda_runtime.h>

// ---------------- problem constants ----------------
#define NL   16
#define DM   1024
#define NH   16
#define NKV  8
#define DH   128
#define SEQ  4096
#define FF   4096
#define VOC  32000

#define NPQ  32    // qkv row partials (32 rows each)
#define NPG  32    // gate/up row partials (32 rows each)
#define NPL  8     // lm row partials (128 rows each)
#define NCH  32    // attention chunks of 128

// ---------------- scratch ----------------
__device__ __align__(16) float g_x[DM];
__device__ __align__(16) float g_qkv_part[NPQ][4096];
__device__ float g_attn_m[NKV][NCH][2];
__device__ float g_attn_l[NKV][NCH][2];
__device__ __align__(16) float g_attn_o[NKV][NCH][2][DH];
__device__ __align__(16) float g_gu_part[NPG][2*FF];
__device__ __align__(16) float g_lm_part[NPL][VOC];
__device__ float g_amax_val[128];
__device__ int   g_amax_idx[128];

__device__ __forceinline__ void fma4(float4& acc, float a, const float4& w) {
    acc.x += a * w.x; acc.y += a * w.y; acc.z += a * w.z; acc.w += a * w.w;
}

// Block-wide rmsnorm rstd from g_x (redundant per block; 4KB L2-hot read).
// 256 threads. Returns rstd to all threads. Uses sm[0..8].
__device__ __forceinline__ float block_rstd(int tid, float* sm) {
    float4 xv = ((const float4*)g_x)[tid];
    float ss = xv.x*xv.x + xv.y*xv.y + xv.z*xv.z + xv.w*xv.w;
    #pragma unroll
    for (int o = 16; o > 0; o >>= 1) ss += __shfl_down_sync(0xffffffffu, ss, o);
    if ((tid & 31) == 0) sm[tid >> 5] = ss;
    __syncthreads();
    if (tid == 0) {
        float t = 0.f;
        #pragma unroll
        for (int i = 0; i < 8; ++i) t += sm[i];
        sm[8] = rsqrtf(t * (1.0f / DM) + 1e-6f);
    }
    __syncthreads();
    return sm[8];
}

// ---------------- KV cache copy (+ g_x init from embed row) ----------------
// dest = out+1 floats (16B-misaligned by 4B). Dest-aligned float4 stores with
// two aligned float4 loads recombined. Head(3)/tail(1) elements scalar.
__global__ void k_copy(const float* __restrict__ a, const float* __restrict__ b,
                       float* __restrict__ oa, float* __restrict__ ob,
                       const float* __restrict__ emb, const int* __restrict__ ids)
{
    if (blockIdx.x == 0)
        ((float4*)g_x)[threadIdx.x] = ((const float4*)(emb + (long)ids[0] * DM))[threadIdx.x];
    const long N = (long)NL * NKV * SEQ * DH;     // 67108864
    const long T = (N - 3) >> 2;                  // dest quads
    long t = (long)blockIdx.x * blockDim.x + threadIdx.x;
    long st = (long)gridDim.x * blockDim.x;
    const float4* a4 = (const float4*)a;
    const float4* b4 = (const float4*)b;
    float4* oa4 = (float4*)(oa + 3);
    float4* ob4 = (float4*)(ob + 3);
    for (; t < T; t += st) {
        float4 A = a4[t], B = a4[t + 1];
        float4 r; r.x = A.w; r.y = B.x; r.z = B.y; r.w = B.z;
        __stcs(oa4 + t, r);
        A = b4[t]; B = b4[t + 1];
        r.x = A.w; r.y = B.x; r.z = B.y; r.w = B.z;
        __stcs(ob4 + t, r);
    }
    if (blockIdx.x == 0 && threadIdx.x < 4) {
        long i = threadIdx.x < 3 ? (long)threadIdx.x : N - 1;
        oa[i] = a[i]; ob[i] = b[i];
    }
}

// ---------------- QKV GEMV (grid (4 coltiles, 32 rowslices), 256 thr) ------
// Folds rmsnorm. cols: [0,2048)=Wq, [2048,3072)=Wk, [3072,4096)=Wv
__global__ void __launch_bounds__(256) k_qkv(
    const float* __restrict__ lnw,
    const float* __restrict__ Wq, const float* __restrict__ Wk,
    const float* __restrict__ Wv)
{
    __shared__ float sm[9];
    __shared__ float sh_n[32];
    int tid = threadIdx.x;
    float rstd = block_rstd(tid, sm);
    int r0 = blockIdx.y * 32;
    if (tid < 32) sh_n[tid] = g_x[r0 + tid] * rstd * lnw[r0 + tid];
    __syncthreads();
    int j = blockIdx.x * 1024 + tid * 4;
    const float* W; int cols, jj;
    if (j < 2048)      { W = Wq; cols = 2048; jj = j; }
    else if (j < 3072) { W = Wk; cols = 1024; jj = j - 2048; }
    else               { W = Wv; cols = 1024; jj = j - 3072; }
    const float* p = W + (long)r0 * cols + jj;
    float4 acc = {0.f,0.f,0.f,0.f};
    #pragma unroll 8
    for (int r = 0; r < 32; ++r) {
        fma4(acc, sh_n[r], *(const float4*)p);
        p += cols;
    }
    *(float4*)&g_qkv_part[blockIdx.y][j] = acc;
}

// ---------------- attention (grid (32 chunks, 8 kv), 256 thr) --------------
// Folds qkv partial reduce + rope + cache-row write + flash-decode partials.
__global__ void __launch_bounds__(256) k_attn(
    const float* __restrict__ pk, const float* __restrict__ pv,
    const int* __restrict__ stepp, const int* __restrict__ plen, int layer,
    float* __restrict__ ok, float* __restrict__ ov)
{
    __shared__ __align__(16) float shq[2*DH];
    __shared__ __align__(16) float shk[DH];
    __shared__ __align__(16) float shv[DH];
    __shared__ float shs[2*128];
    __shared__ float red[8];
    __shared__ float shm[2];
    int pos = stepp[0] + plen[0];
    int kv = blockIdx.y, ch = blockIdx.x;
    int s0 = ch << 7;
    int tid = threadIdx.x;
    if (s0 > pos) {
        if (tid < 2) g_attn_l[kv][ch][tid] = 0.f;
        return;
    }
    int smax = (pos < s0 + 127) ? pos : s0 + 127;
    bool haspos = (ch == (pos >> 7));
    {
        int h = tid >> 7, d = tid & 127;
        float a = 0.f;
        #pragma unroll 8
        for (int i = 0; i < NPQ; ++i) a += g_qkv_part[i][(kv*2 + h)*DH + d];
        shq[h*DH + d] = a;
    }
    if (haspos) {
        int off = (tid < 128) ? (2048 + kv*DH + tid) : (3072 + kv*DH + tid - 128);
        float a = 0.f;
        #pragma unroll 8
        for (int i = 0; i < NPQ; ++i) a += g_qkv_part[i][off];
        if (tid < 128) shk[tid] = a; else shv[tid - 128] = a;
    }
    __syncthreads();
    const float SCALE = 0.08838834764831845f;   // 1/sqrt(128)
    const float LF = 0.14391156831212785f;      // ln(10000)/64
    if (tid < 128) {
        int h = tid >> 6, i = tid & 63;
        float ang = (float)pos * expf(-(float)i * LF);
        float c, s; sincosf(ang, &s, &c);
        float x1 = shq[h*128 + i], x2 = shq[h*128 + i + 64];
        shq[h*128 + i]      = (x1*c - x2*s) * SCALE;
        shq[h*128 + i + 64] = (x2*c + x1*s) * SCALE;
    } else if (haspos && tid < 192) {
        int i = tid - 128;
        float ang = (float)pos * expf(-(float)i * LF);
        float c, s; sincosf(ang, &s, &c);
        float k1 = shk[i], k2 = shk[i + 64];
        shk[i]      = k1*c - k2*s;
        shk[i + 64] = k2*c + k1*s;
    }
    __syncthreads();
    if (haspos) {
        long rb = (((long)layer * NKV + kv) * SEQ + pos) * DH;
        if (tid < 128) ok[rb + tid] = shk[tid];
        else           ov[rb + tid - 128] = shv[tid - 128];
    }
    int warp = tid >> 5, lane = tid & 31;
    float4 q0 = ((const float4*)shq)[lane];
    float4 q1 = ((const float4*)(shq + 128))[lane];
    long kb = ((long)layer * NKV + kv) * SEQ * DH;
    #pragma unroll 2
    for (int it = 0; it < 16; ++it) {
        int sl = (it << 3) + warp;
        int si = s0 + sl;
        if (si <= smax) {
            float4 kk;
            if (si == pos) kk = ((const float4*)shk)[lane];
            else           kk = *(const float4*)(pk + kb + (long)si*DH + lane*4);
            float d0 = q0.x*kk.x + q0.y*kk.y + q0.z*kk.z + q0.w*kk.w;
            float d1 = q1.x*kk.x + q1.y*kk.y + q1.z*kk.z + q1.w*kk.w;
            #pragma unroll
            for (int o = 16; o > 0; o >>= 1) {
                d0 += __shfl_down_sync(0xffffffffu, d0, o);
                d1 += __shfl_down_sync(0xffffffffu, d1, o);
            }
            if (lane == 0) { shs[sl] = d0; shs[128 + sl] = d1; }
        } else if (lane == 0) {
            shs[sl] = -1e30f; shs[128 + sl] = -1e30f;
        }
    }
    __syncthreads();
    int h = tid >> 7, d = tid & 127;
    float v = shs[h*128 + d];
    float m = v;
    #pragma unroll
    for (int o = 16; o > 0; o >>= 1) m = fmaxf(m, __shfl_down_sync(0xffffffffu, m, o));
    if (lane == 0) red[warp] = m;
    __syncthreads();
    if (tid < 2)
        shm[tid] = fmaxf(fmaxf(red[tid*4], red[tid*4+1]), fmaxf(red[tid*4+2], red[tid*4+3]));
    __syncthreads();
    float p = expf(v - shm[h]);
    shs[h*128 + d] = p;
    float l = p;
    #pragma unroll
    for (int o = 16; o > 0; o >>= 1) l += __shfl_down_sync(0xffffffffu, l, o);
    if (lane == 0) red[warp] = l;
    __syncthreads();
    if (tid < 2) {
        g_attn_m[kv][ch][tid] = shm[tid];
        g_attn_l[kv][ch][tid] = red[tid*4] + red[tid*4+1] + red[tid*4+2] + red[tid*4+3];
    }
    int count = smax - s0 + 1;
    int nglob = haspos ? count - 1 : count;
    const float* pvp = pv + kb + (long)s0*DH + d;
    float acc = 0.f;
    int s = 0;
    for (; s + 7 < nglob; s += 8) {
        float acc2 = 0.f;
        #pragma unroll
        for (int u = 0; u < 8; u += 2) {
            acc  += shs[h*128 + s+u]   * pvp[(long)(s+u)*DH];
            acc2 += shs[h*128 + s+u+1] * pvp[(long)(s+u+1)*DH];
        }
        acc += acc2;
    }
    for (; s < nglob; ++s) acc += shs[h*128 + s] * pvp[(long)s*DH];
    if (haspos) acc += shs[h*128 + count - 1] * shv[d];
    g_attn_o[kv][ch][h][d] = acc;
}

// ---------------- Wo GEMV + softmax combine -> atomicAdd g_x (64 blocks) ---
__global__ void __launch_bounds__(256) k_wo(const float* __restrict__ Wo)
{
    __shared__ float ml[64];
    __shared__ float w[32];
    __shared__ float av[32];
    __shared__ float idn;
    int r0 = blockIdx.x * 32;
    int p = r0 >> 7, kv = p >> 1, hh = p & 1, db = r0 & 127;
    int tid = threadIdx.x;
    if (tid < 32) { ml[tid] = g_attn_m[kv][tid][hh]; ml[32 + tid] = g_attn_l[kv][tid][hh]; }
    __syncthreads();
    if (tid == 0) {
        float M = -1e30f;
        for (int c = 0; c < NCH; ++c) if (ml[32+c] > 0.f) M = fmaxf(M, ml[c]);
        float den = 0.f;
        for (int c = 0; c < NCH; ++c) {
            float wv = (ml[32+c] > 0.f) ? expf(ml[c] - M) : 0.f;
            w[c] = wv; den += wv * ml[32+c];
        }
        idn = 1.f / den;
    }
    __syncthreads();
    if (tid < 32) {
        float num = 0.f;
        #pragma unroll
        for (int c = 0; c < NCH; ++c) {
            float wv = w[c];
            if (wv != 0.f) num += wv * g_attn_o[kv][c][hh][db + tid];
        }
        av[tid] = num * idn;
    }
    __syncthreads();
    int j = tid * 4;
    const float* pw = Wo + (long)r0 * DM + j;
    float4 acc = {0.f,0.f,0.f,0.f};
    #pragma unroll 8
    for (int r = 0; r < 32; ++r)
        fma4(acc, av[r], *(const float4*)(pw + (long)r * DM));
    atomicAdd(&g_x[j],     acc.x);
    atomicAdd(&g_x[j + 1], acc.y);
    atomicAdd(&g_x[j + 2], acc.z);
    atomicAdd(&g_x[j + 3], acc.w);
}

// ---------------- gate/up GEMV (grid (8, 32 rowslices), 256 thr) -----------
__global__ void __launch_bounds__(256) k_gateup(
    const float* __restrict__ lnw,
    const float* __restrict__ Wg, const float* __restrict__ Wu)
{
    __shared__ float sm[9];
    __shared__ float sh_n[32];
    int tid = threadIdx.x;
    float rstd = block_rstd(tid, sm);
    int r0 = blockIdx.y * 32;
    if (tid < 32) sh_n[tid] = g_x[r0 + tid] * rstd * lnw[r0 + tid];
    __syncthreads();
    int j = blockIdx.x * 1024 + tid * 4;
    const float* W; int jj;
    if (j < FF) { W = Wg; jj = j; } else { W = Wu; jj = j - FF; }
    const float* p = W + (long)r0 * FF + jj;
    float4 acc = {0.f,0.f,0.f,0.f};
    #pragma unroll 8
    for (int r = 0; r < 32; ++r) {
        fma4(acc, sh_n[r], *(const float4*)p);
        p += FF;
    }
    *(float4*)&g_gu_part[blockIdx.y][j] = acc;
}

// ---------------- Wd GEMV + silu -> atomicAdd g_x (128 blocks) -------------
__global__ void __launch_bounds__(256) k_wd(const float* __restrict__ Wd)
{
    __shared__ float sh_h[32];
    int r0 = blockIdx.x * 32;
    int tid = threadIdx.x;
    if (tid < 32) {
        float g = 0.f, u = 0.f;
        #pragma unroll 8
        for (int i = 0; i < NPG; ++i) {
            g += g_gu_part[i][r0 + tid];
            u += g_gu_part[i][FF + r0 + tid];
        }
        sh_h[tid] = (g / (1.f + expf(-g))) * u;
    }
    __syncthreads();
    int j = tid * 4;
    const float* pw = Wd + (long)r0 * DM + j;
    float4 acc = {0.f,0.f,0.f,0.f};
    #pragma unroll 8
    for (int r = 0; r < 32; ++r)
        fma4(acc, sh_h[r], *(const float4*)(pw + (long)r * DM));
    atomicAdd(&g_x[j],     acc.x);
    atomicAdd(&g_x[j + 1], acc.y);
    atomicAdd(&g_x[j + 2], acc.z);
    atomicAdd(&g_x[j + 3], acc.w);
}

// ---------------- LM head GEMV (grid (32, 8 rowslices), 256 thr) -----------
__global__ void __launch_bounds__(256) k_lm(
    const float* __restrict__ lnf, const float* __restrict__ Wlm)
{
    __shared__ float sm[9];
    __shared__ float n[128];
    int tid = threadIdx.x;
    float rstd = block_rstd(tid, sm);
    int r0 = blockIdx.y * 128;
    if (tid < 128) n[tid] = g_x[r0 + tid] * rstd * lnf[r0 + tid];
    __syncthreads();
    int j = blockIdx.x * 1024 + tid * 4;
    if (j >= VOC) return;
    const float* p = Wlm + (long)r0 * VOC + j;
    float4 acc = {0.f,0.f,0.f,0.f};
    #pragma unroll 8
    for (int r = 0; r < 128; ++r) {
        fma4(acc, n[r], *(const float4*)p);
        p += VOC;
    }
    *(float4*)&g_lm_part[blockIdx.y][j] = acc;
}

// ---------------- argmax ----------------
__global__ void __launch_bounds__(256) k_amax1()
{
    __shared__ float sv[256];
    __shared__ int   si[256];
    int t = threadIdx.x;
    int j = blockIdx.x * 256 + t;
    float v = 0.f;
    #pragma unroll
    for (int i = 0; i < NPL; ++i) v += g_lm_part[i][j];
    sv[t] = v; si[t] = j;
    __syncthreads();
    for (int o = 128; o > 0; o >>= 1) {
        if (t < o) {
            float v2 = sv[t + o]; int i2 = si[t + o];
            if (v2 > sv[t] || (v2 == sv[t] && i2 < si[t])) { sv[t] = v2; si[t] = i2; }
        }
        __syncthreads();
    }
    if (t == 0) { g_amax_val[blockIdx.x] = sv[0]; g_amax_idx[blockIdx.x] = si[0]; }
}

__global__ void __launch_bounds__(128) k_amax2(float* __restrict__ out)
{
    __shared__ float sv[128];
    __shared__ int   si[128];
    int t = threadIdx.x;
    if (t < 125) { sv[t] = g_amax_val[t]; si[t] = g_amax_idx[t]; }
    else         { sv[t] = -1e38f;        si[t] = 0x7fffffff; }
    __syncthreads();
    for (int o = 64; o > 0; o >>= 1) {
        if (t < o) {
            float v2 = sv[t + o]; int i2 = si[t + o];
            if (v2 > sv[t] || (v2 == sv[t] && i2 < si[t])) { sv[t] = v2; si[t] = i2; }
        }
        __syncthreads();
    }
    if (t == 0) out[0] = (float)si[0];
}

// ---------------- launch ----------------
extern "C" void kernel_launch(void* const* d_in, const int* in_sizes, int n_in,
                              void* d_out, int out_size)
{
    const int*   ids  = (const int*)  d_in[0];
    const int*   step = (const int*)  d_in[1];
    const int*   plen = (const int*)  d_in[2];
    const float* pk   = (const float*)d_in[3];
    const float* pv   = (const float*)d_in[4];
    const float* emb  = (const float*)d_in[5];
    const float* Wq   = (const float*)d_in[6];
    const float* Wk   = (const float*)d_in[7];
    const float* Wv   = (const float*)d_in[8];
    const float* Wo   = (const float*)d_in[9];
    const float* Wg   = (const float*)d_in[10];
    const float* Wu   = (const float*)d_in[11];
    const float* Wd   = (const float*)d_in[12];
    const float* ln1  = (const float*)d_in[13];
    const float* ln2  = (const float*)d_in[14];
    const float* lnf  = (const float*)d_in[15];
    const float* Wlm  = (const float*)d_in[16];

    float* out = (float*)d_out;
    const long CACHE = (long)NL * NKV * SEQ * DH;
    float* ok = out + 1;
    float* ov = out + 1 + CACHE;

    k_copy<<<2048, 256>>>(pk, pv, ok, ov, emb, ids);

    for (int l = 0; l < NL; ++l) {
        k_qkv<<<dim3(4, NPQ), 256>>>(
            ln1 + (long)l * DM,
            Wq + (long)l * DM * 2048,
            Wk + (long)l * DM * 1024,
            Wv + (long)l * DM * 1024);
        k_attn<<<dim3(NCH, NKV), 256>>>(pk, pv, step, plen, l, ok, ov);
        k_wo<<<64, 256>>>(Wo + (long)l * 2048 * DM);
        k_gateup<<<dim3(8, NPG), 256>>>(
            ln2 + (long)l * DM,
            Wg + (long)l * DM * FF,
            Wu + (long)l * DM * FF);
        k_wd<<<128, 256>>>(Wd + (long)l * FF * DM);
    }

    k_lm<<<dim3(32, NPL), 256>>>(lnf, Wlm);
    k_amax1<<<125, 256>>>();
    k_amax2<<<1, 128>>>(out);
}

// round 12
// speedup vs baseline: 1.8982x; 1.0228x over previous
#include <cuda_runtime.h>

// ---------------- problem constants ----------------
#define NL   16
#define DM   1024
#define NH   16
#define NKV  8
#define DH   128
#define SEQ  4096
#define FF   4096
#define VOC  32000

#define NPQ  64    // qkv row partials (16 rows each)
#define NPG  64    // gate/up row partials (16 rows each)
#define NPL  16    // lm row partials (64 rows each)
#define NCH  32    // attention chunks of 128

// ---------------- scratch ----------------
__device__ __align__(16) float g_x[DM];
__device__ __align__(16) float g_qkv_part[NPQ][4096];
__device__ float g_attn_m[NKV][NCH][2];
__device__ float g_attn_l[NKV][NCH][2];
__device__ __align__(16) float g_attn_o[NKV][NCH][2][DH];
__device__ __align__(16) float g_gu_part[NPG][2*FF];
__device__ __align__(16) float g_lm_part[NPL][VOC];
__device__ float g_amax_val[128];
__device__ int   g_amax_idx[128];

__device__ __forceinline__ void fma4(float4& acc, float a, const float4& w) {
    acc.x += a * w.x; acc.y += a * w.y; acc.z += a * w.z; acc.w += a * w.w;
}

// 16-row GEMV tile: burst-load 16 float4 (64 lines/warp in flight), then fma.
__device__ __forceinline__ void gemv16(float4& acc, const float* __restrict__ p,
                                       long stride, const float* __restrict__ coef)
{
    float4 wv[16];
    #pragma unroll
    for (int r = 0; r < 16; ++r)
        wv[r] = *(const float4*)(p + (long)r * stride);
    #pragma unroll
    for (int r = 0; r < 16; ++r)
        fma4(acc, coef[r], wv[r]);
}

// Block-wide rmsnorm rstd from g_x (256 threads). Uses sm[0..8].
__device__ __forceinline__ float block_rstd(int tid, float* sm) {
    float4 xv = ((const float4*)g_x)[tid];
    float ss = xv.x*xv.x + xv.y*xv.y + xv.z*xv.z + xv.w*xv.w;
    #pragma unroll
    for (int o = 16; o > 0; o >>= 1) ss += __shfl_down_sync(0xffffffffu, ss, o);
    if ((tid & 31) == 0) sm[tid >> 5] = ss;
    __syncthreads();
    if (tid == 0) {
        float t = 0.f;
        #pragma unroll
        for (int i = 0; i < 8; ++i) t += sm[i];
        sm[8] = rsqrtf(t * (1.0f / DM) + 1e-6f);
    }
    __syncthreads();
    return sm[8];
}

// ---------------- KV cache copy (+ g_x init from embed row) ----------------
__global__ void k_copy(const float* __restrict__ a, const float* __restrict__ b,
                       float* __restrict__ oa, float* __restrict__ ob,
                       const float* __restrict__ emb, const int* __restrict__ ids)
{
    if (blockIdx.x == 0)
        ((float4*)g_x)[threadIdx.x] = ((const float4*)(emb + (long)ids[0] * DM))[threadIdx.x];
    const long N = (long)NL * NKV * SEQ * DH;     // 67108864
    const long T = (N - 3) >> 2;                  // dest quads
    long t = (long)blockIdx.x * blockDim.x + threadIdx.x;
    long st = (long)gridDim.x * blockDim.x;
    const float4* a4 = (const float4*)a;
    const float4* b4 = (const float4*)b;
    float4* oa4 = (float4*)(oa + 3);
    float4* ob4 = (float4*)(ob + 3);
    for (; t < T; t += st) {
        float4 A = a4[t], B = a4[t + 1];
        float4 r; r.x = A.w; r.y = B.x; r.z = B.y; r.w = B.z;
        __stcs(oa4 + t, r);
        A = b4[t]; B = b4[t + 1];
        r.x = A.w; r.y = B.x; r.z = B.y; r.w = B.z;
        __stcs(ob4 + t, r);
    }
    if (blockIdx.x == 0 && threadIdx.x < 4) {
        long i = threadIdx.x < 3 ? (long)threadIdx.x : N - 1;
        oa[i] = a[i]; ob[i] = b[i];
    }
}

// ---------------- QKV GEMV (grid (4 coltiles, 64 rowslices of 16)) ---------
__global__ void __launch_bounds__(256) k_qkv(
    const float* __restrict__ lnw,
    const float* __restrict__ Wq, const float* __restrict__ Wk,
    const float* __restrict__ Wv)
{
    __shared__ float sm[9];
    __shared__ float sh_n[16];
    int tid = threadIdx.x;
    float rstd = block_rstd(tid, sm);
    int r0 = blockIdx.y * 16;
    if (tid < 16) sh_n[tid] = g_x[r0 + tid] * rstd * lnw[r0 + tid];
    __syncthreads();
    int j = blockIdx.x * 1024 + tid * 4;
    const float* W; int cols, jj;
    if (j < 2048)      { W = Wq; cols = 2048; jj = j; }
    else if (j < 3072) { W = Wk; cols = 1024; jj = j - 2048; }
    else               { W = Wv; cols = 1024; jj = j - 3072; }
    float4 acc = {0.f,0.f,0.f,0.f};
    gemv16(acc, W + (long)r0 * cols + jj, cols, sh_n);
    *(float4*)&g_qkv_part[blockIdx.y][j] = acc;
}

// ---------------- attention (grid (32 chunks, 8 kv), 256 thr) --------------
__global__ void __launch_bounds__(256) k_attn(
    const float* __restrict__ pk, const float* __restrict__ pv,
    const int* __restrict__ stepp, const int* __restrict__ plen, int layer,
    float* __restrict__ ok, float* __restrict__ ov)
{
    __shared__ __align__(16) float shq[2*DH];
    __shared__ __align__(16) float shk[DH];
    __shared__ __align__(16) float shv[DH];
    __shared__ float shs[2*128];
    __shared__ float red[8];
    __shared__ float shm[2];
    int pos = stepp[0] + plen[0];
    int kv = blockIdx.y, ch = blockIdx.x;
    int s0 = ch << 7;
    int tid = threadIdx.x;
    if (s0 > pos) {
        if (tid < 2) g_attn_l[kv][ch][tid] = 0.f;
        return;
    }
    int smax = (pos < s0 + 127) ? pos : s0 + 127;
    bool haspos = (ch == (pos >> 7));
    {
        int h = tid >> 7, d = tid & 127;
        float a = 0.f;
        #pragma unroll 16
        for (int i = 0; i < NPQ; ++i) a += g_qkv_part[i][(kv*2 + h)*DH + d];
        shq[h*DH + d] = a;
    }
    if (haspos) {
        int off = (tid < 128) ? (2048 + kv*DH + tid) : (3072 + kv*DH + tid - 128);
        float a = 0.f;
        #pragma unroll 16
        for (int i = 0; i < NPQ; ++i) a += g_qkv_part[i][off];
        if (tid < 128) shk[tid] = a; else shv[tid - 128] = a;
    }
    __syncthreads();
    const float SCALE = 0.08838834764831845f;   // 1/sqrt(128)
    const float LF = 0.14391156831212785f;      // ln(10000)/64
    if (tid < 128) {
        int h = tid >> 6, i = tid & 63;
        float ang = (float)pos * expf(-(float)i * LF);
        float c, s; sincosf(ang, &s, &c);
        float x1 = shq[h*128 + i], x2 = shq[h*128 + i + 64];
        shq[h*128 + i]      = (x1*c - x2*s) * SCALE;
        shq[h*128 + i + 64] = (x2*c + x1*s) * SCALE;
    } else if (haspos && tid < 192) {
        int i = tid - 128;
        float ang = (float)pos * expf(-(float)i * LF);
        float c, s; sincosf(ang, &s, &c);
        float k1 = shk[i], k2 = shk[i + 64];
        shk[i]      = k1*c - k2*s;
        shk[i + 64] = k2*c + k1*s;
    }
    __syncthreads();
    if (haspos) {
        long rb = (((long)layer * NKV + kv) * SEQ + pos) * DH;
        if (tid < 128) ok[rb + tid] = shk[tid];
        else           ov[rb + tid - 128] = shv[tid - 128];
    }
    int warp = tid >> 5, lane = tid & 31;
    float4 q0 = ((const float4*)shq)[lane];
    float4 q1 = ((const float4*)(shq + 128))[lane];
    long kb = ((long)layer * NKV + kv) * SEQ * DH;
    #pragma unroll 2
    for (int it = 0; it < 16; ++it) {
        int sl = (it << 3) + warp;
        int si = s0 + sl;
        if (si <= smax) {
            float4 kk;
            if (si == pos) kk = ((const float4*)shk)[lane];
            else           kk = *(const float4*)(pk + kb + (long)si*DH + lane*4);
            float d0 = q0.x*kk.x + q0.y*kk.y + q0.z*kk.z + q0.w*kk.w;
            float d1 = q1.x*kk.x + q1.y*kk.y + q1.z*kk.z + q1.w*kk.w;
            #pragma unroll
            for (int o = 16; o > 0; o >>= 1) {
                d0 += __shfl_down_sync(0xffffffffu, d0, o);
                d1 += __shfl_down_sync(0xffffffffu, d1, o);
            }
            if (lane == 0) { shs[sl] = d0; shs[128 + sl] = d1; }
        } else if (lane == 0) {
            shs[sl] = -1e30f; shs[128 + sl] = -1e30f;
        }
    }
    __syncthreads();
    int h = tid >> 7, d = tid & 127;
    float v = shs[h*128 + d];
    float m = v;
    #pragma unroll
    for (int o = 16; o > 0; o >>= 1) m = fmaxf(m, __shfl_down_sync(0xffffffffu, m, o));
    if (lane == 0) red[warp] = m;
    __syncthreads();
    if (tid < 2)
        shm[tid] = fmaxf(fmaxf(red[tid*4], red[tid*4+1]), fmaxf(red[tid*4+2], red[tid*4+3]));
    __syncthreads();
    float p = expf(v - shm[h]);
    shs[h*128 + d] = p;
    float l = p;
    #pragma unroll
    for (int o = 16; o > 0; o >>= 1) l += __shfl_down_sync(0xffffffffu, l, o);
    if (lane == 0) red[warp] = l;
    __syncthreads();
    if (tid < 2) {
        g_attn_m[kv][ch][tid] = shm[tid];
        g_attn_l[kv][ch][tid] = red[tid*4] + red[tid*4+1] + red[tid*4+2] + red[tid*4+3];
    }
    int count = smax - s0 + 1;
    int nglob = haspos ? count - 1 : count;
    const float* pvp = pv + kb + (long)s0*DH + d;
    float acc = 0.f;
    int s = 0;
    for (; s + 7 < nglob; s += 8) {
        float acc2 = 0.f;
        #pragma unroll
        for (int u = 0; u < 8; u += 2) {
            acc  += shs[h*128 + s+u]   * pvp[(long)(s+u)*DH];
            acc2 += shs[h*128 + s+u+1] * pvp[(long)(s+u+1)*DH];
        }
        acc += acc2;
    }
    for (; s < nglob; ++s) acc += shs[h*128 + s] * pvp[(long)s*DH];
    if (haspos) acc += shs[h*128 + count - 1] * shv[d];
    g_attn_o[kv][ch][h][d] = acc;
}

// ---------------- Wo GEMV + softmax combine -> atomicAdd g_x (128 blocks) --
__global__ void __launch_bounds__(256) k_wo(const float* __restrict__ Wo)
{
    __shared__ float shw[NCH];
    __shared__ float av[16];
    __shared__ float idn;
    int r0 = blockIdx.x * 16;
    int p = r0 >> 7, kv = p >> 1, hh = p & 1, db = r0 & 127;
    int tid = threadIdx.x;
    if (tid < 32) {
        float m = g_attn_m[kv][tid][hh];
        float l = g_attn_l[kv][tid][hh];
        float mm = (l > 0.f) ? m : -1e30f;
        float M = mm;
        #pragma unroll
        for (int o = 16; o > 0; o >>= 1) M = fmaxf(M, __shfl_xor_sync(0xffffffffu, M, o));
        float w = (l > 0.f) ? expf(m - M) : 0.f;
        float dl = w * l;
        #pragma unroll
        for (int o = 16; o > 0; o >>= 1) dl += __shfl_xor_sync(0xffffffffu, dl, o);
        shw[tid] = w;
        if (tid == 0) idn = 1.f / dl;
    }
    __syncthreads();
    if (tid < 16) {
        float num = 0.f;
        #pragma unroll
        for (int c = 0; c < NCH; ++c) {
            float wv = shw[c];
            if (wv != 0.f) num += wv * g_attn_o[kv][c][hh][db + tid];
        }
        av[tid] = num * idn;
    }
    __syncthreads();
    int j = tid * 4;
    float4 acc = {0.f,0.f,0.f,0.f};
    gemv16(acc, Wo + (long)r0 * DM + j, DM, av);
    atomicAdd(&g_x[j],     acc.x);
    atomicAdd(&g_x[j + 1], acc.y);
    atomicAdd(&g_x[j + 2], acc.z);
    atomicAdd(&g_x[j + 3], acc.w);
}

// ---------------- gate/up GEMV (grid (8 coltiles, 64 rowslices of 16)) -----
__global__ void __launch_bounds__(256) k_gateup(
    const float* __restrict__ lnw,
    const float* __restrict__ Wg, const float* __restrict__ Wu)
{
    __shared__ float sm[9];
    __shared__ float sh_n[16];
    int tid = threadIdx.x;
    float rstd = block_rstd(tid, sm);
    int r0 = blockIdx.y * 16;
    if (tid < 16) sh_n[tid] = g_x[r0 + tid] * rstd * lnw[r0 + tid];
    __syncthreads();
    int j = blockIdx.x * 1024 + tid * 4;
    const float* W; int jj;
    if (j < FF) { W = Wg; jj = j; } else { W = Wu; jj = j - FF; }
    float4 acc = {0.f,0.f,0.f,0.f};
    gemv16(acc, W + (long)r0 * FF + jj, FF, sh_n);
    *(float4*)&g_gu_part[blockIdx.y][j] = acc;
}

// ---------------- Wd GEMV + silu -> atomicAdd g_x (256 blocks of 16 rows) --
__global__ void __launch_bounds__(256) k_wd(const float* __restrict__ Wd)
{
    __shared__ float sh_g[64], sh_u[64];
    __shared__ float sh_h[16];
    int r0 = blockIdx.x * 16;
    int tid = threadIdx.x;
    if (tid < 64) {
        int row = tid & 15, grp = tid >> 4;     // 4 groups of 16 partials
        float g = 0.f, u = 0.f;
        #pragma unroll
        for (int i = 0; i < 16; ++i) {
            int pi = grp * 16 + i;
            g += g_gu_part[pi][r0 + row];
            u += g_gu_part[pi][FF + r0 + row];
        }
        sh_g[tid] = g; sh_u[tid] = u;
    }
    __syncthreads();
    if (tid < 16) {
        float g = sh_g[tid] + sh_g[16 + tid] + sh_g[32 + tid] + sh_g[48 + tid];
        float u = sh_u[tid] + sh_u[16 + tid] + sh_u[32 + tid] + sh_u[48 + tid];
        sh_h[tid] = (g / (1.f + expf(-g))) * u;
    }
    __syncthreads();
    int j = tid * 4;
    float4 acc = {0.f,0.f,0.f,0.f};
    gemv16(acc, Wd + (long)r0 * DM + j, DM, sh_h);
    atomicAdd(&g_x[j],     acc.x);
    atomicAdd(&g_x[j + 1], acc.y);
    atomicAdd(&g_x[j + 2], acc.z);
    atomicAdd(&g_x[j + 3], acc.w);
}

// ---------------- LM head GEMV (grid (32 coltiles, 16 rowslices of 64)) ----
__global__ void __launch_bounds__(256) k_lm(
    const float* __restrict__ lnf, const float* __restrict__ Wlm)
{
    __shared__ float sm[9];
    __shared__ float n[64];
    int tid = threadIdx.x;
    float rstd = block_rstd(tid, sm);
    int r0 = blockIdx.y * 64;
    if (tid < 64) n[tid] = g_x[r0 + tid] * rstd * lnf[r0 + tid];
    __syncthreads();
    int j = blockIdx.x * 1024 + tid * 4;
    if (j >= VOC) return;
    float4 acc = {0.f,0.f,0.f,0.f};
    #pragma unroll
    for (int c = 0; c < 4; ++c)
        gemv16(acc, Wlm + ((long)r0 + c*16) * VOC + j, VOC, n + c*16);
    *(float4*)&g_lm_part[blockIdx.y][j] = acc;
}

// ---------------- argmax ----------------
__global__ void __launch_bounds__(256) k_amax1()
{
    __shared__ float sv[256];
    __shared__ int   si[256];
    int t = threadIdx.x;
    int j = blockIdx.x * 256 + t;
    float v = 0.f;
    #pragma unroll
    for (int i = 0; i < NPL; ++i) v += g_lm_part[i][j];
    sv[t] = v; si[t] = j;
    __syncthreads();
    for (int o = 128; o > 0; o >>= 1) {
        if (t < o) {
            float v2 = sv[t + o]; int i2 = si[t + o];
            if (v2 > sv[t] || (v2 == sv[t] && i2 < si[t])) { sv[t] = v2; si[t] = i2; }
        }
        __syncthreads();
    }
    if (t == 0) { g_amax_val[blockIdx.x] = sv[0]; g_amax_idx[blockIdx.x] = si[0]; }
}

__global__ void __launch_bounds__(128) k_amax2(float* __restrict__ out)
{
    __shared__ float sv[128];
    __shared__ int   si[128];
    int t = threadIdx.x;
    if (t < 125) { sv[t] = g_amax_val[t]; si[t] = g_amax_idx[t]; }
    else         { sv[t] = -1e38f;        si[t] = 0x7fffffff; }
    __syncthreads();
    for (int o = 64; o > 0; o >>= 1) {
        if (t < o) {
            float v2 = sv[t + o]; int i2 = si[t + o];
            if (v2 > sv[t] || (v2 == sv[t] && i2 < si[t])) { sv[t] = v2; si[t] = i2; }
        }
        __syncthreads();
    }
    if (t == 0) out[0] = (float)si[0];
}

// ---------------- launch ----------------
extern "C" void kernel_launch(void* const* d_in, const int* in_sizes, int n_in,
                              void* d_out, int out_size)
{
    const int*   ids  = (const int*)  d_in[0];
    const int*   step = (const int*)  d_in[1];
    const int*   plen = (const int*)  d_in[2];
    const float* pk   = (const float*)d_in[3];
    const float* pv   = (const float*)d_in[4];
    const float* emb  = (const float*)d_in[5];
    const float* Wq   = (const float*)d_in[6];
    const float* Wk   = (const float*)d_in[7];
    const float* Wv   = (const float*)d_in[8];
    const float* Wo   = (const float*)d_in[9];
    const float* Wg   = (const float*)d_in[10];
    const float* Wu   = (const float*)d_in[11];
    const float* Wd   = (const float*)d_in[12];
    const float* ln1  = (const float*)d_in[13];
    const float* ln2  = (const float*)d_in[14];
    const float* lnf  = (const float*)d_in[15];
    const float* Wlm  = (const float*)d_in[16];

    float* out = (float*)d_out;
    const long CACHE = (long)NL * NKV * SEQ * DH;
    float* ok = out + 1;
    float* ov = out + 1 + CACHE;

    k_copy<<<2048, 256>>>(pk, pv, ok, ov, emb, ids);

    for (int l = 0; l < NL; ++l) {
        k_qkv<<<dim3(4, NPQ), 256>>>(
            ln1 + (long)l * DM,
            Wq + (long)l * DM * 2048,
            Wk + (long)l * DM * 1024,
            Wv + (long)l * DM * 1024);
        k_attn<<<dim3(NCH, NKV), 256>>>(pk, pv, step, plen, l, ok, ov);
        k_wo<<<128, 256>>>(Wo + (long)l * 2048 * DM);
        k_gateup<<<dim3(8, NPG), 256>>>(
            ln2 + (long)l * DM,
            Wg + (long)l * DM * FF,
            Wu + (long)l * DM * FF);
        k_wd<<<256, 256>>>(Wd + (long)l * FF * DM);
    }

    k_lm<<<dim3(32, NPL), 256>>>(lnf, Wlm);
    k_amax1<<<125, 256>>>();
    k_amax2<<<1, 128>>>(out);
}